// round 2
// baseline (speedup 1.0000x reference)
#include <cuda_runtime.h>
#include <math.h>

#define Bb 2
#define Ss 128
#define Hh 768
#define Cc 5
#define NEGV (-1024.0f)
#define Mm (Bb*Ss)          // 256
#define NTOT (Hh + Cc*Hh)   // 4608
#define NROWS (Bb*Ss*Cc)    // 1280
#define OUTN (Bb*Ss*Cc*Ss)  // 163840

__device__ float g_hp[Mm*Hh];
__device__ float g_ha[Mm*Cc*Hh];
__device__ float g_out[OUTN];
__device__ float g_rnum[NROWS];
__device__ float g_rden[NROWS];
__device__ int   g_ngMode;   // 0 = uint8, 1 = int32, 2 = float32

__device__ __forceinline__ float tanh_fast(float x){
    float y; asm("tanh.approx.f32 %0, %1;" : "=f"(y) : "f"(x)); return y;
}

// ---------------------------------------------------------------------------
// Detect the storage dtype of the bool ng_token_mask buffer.
//   int32  {0,1}: nonzero bytes only at offset%4==0 (little-endian)
//   float32{0,1}: 0x3F bytes at offset%4==3, 0x80 at offset%4==2
//   uint8  {0,1}: random nonzero bytes at all offsets
// ---------------------------------------------------------------------------
__global__ __launch_bounds__(256) void k_detect(const unsigned char* __restrict__ ng){
    __shared__ int s_b1, s_f3;
    if (threadIdx.x == 0){ s_b1 = 0; s_f3 = 0; }
    __syncthreads();
    int b1 = 0, f3 = 0;
    for (int i = threadIdx.x; i < 16384; i += 256){
        unsigned char v = ng[i];
        int o = i & 3;
        if (o == 1 && v) b1 = 1;
        if (o == 3 && v == 0x3F) f3 = 1;
    }
    if (b1) s_b1 = 1;
    if (f3) s_f3 = 1;
    __syncthreads();
    if (threadIdx.x == 0)
        g_ngMode = s_b1 ? 0 : (s_f3 ? 2 : 1);
}

__device__ __forceinline__ bool ng_bit(const void* ng, int idx, int mode){
    if (mode == 1) return ((const int*)ng)[idx] != 0;
    if (mode == 2) return ((const float*)ng)[idx] != 0.0f;
    return ((const unsigned char*)ng)[idx] != 0;
}

// ---------------------------------------------------------------------------
// Kernel A: fused GEMM  Y[m,n] = sum_k X[m,k]*Wcat[n,k] + bias[n]
//   n < H      -> g_hp[m*H + n]            (W_prd, b_prd)
//   n >= H     -> g_ha[m*C*H + (n-H)]      (W_arg, b_arg)
// ---------------------------------------------------------------------------
#define BM 64
#define BN 64
#define BK 16

__global__ __launch_bounds__(256) void k_gemm(const float* __restrict__ X,
        const float* __restrict__ Wp, const float* __restrict__ bp,
        const float* __restrict__ Wa, const float* __restrict__ ba){
    __shared__ float As[BK][BM+4];
    __shared__ float Bs[BK][BN+4];
    int n0 = blockIdx.x * BN;
    int m0 = blockIdx.y * BM;
    int tid = threadIdx.x;
    int tx = tid & 15, ty = tid >> 4;
    float acc[4][4] = {};
    for (int k0 = 0; k0 < Hh; k0 += BK){
        #pragma unroll
        for (int i = 0; i < 4; i++){
            int idx = tid + i*256;
            int ml = idx >> 4, kl = idx & 15;
            As[kl][ml] = X[(m0+ml)*Hh + k0 + kl];
        }
        #pragma unroll
        for (int i = 0; i < 4; i++){
            int idx = tid + i*256;
            int nl = idx >> 4, kl = idx & 15;
            int n = n0 + nl;
            Bs[kl][nl] = (n < Hh) ? Wp[n*Hh + k0 + kl]
                                  : Wa[(n-Hh)*Hh + k0 + kl];
        }
        __syncthreads();
        #pragma unroll
        for (int k = 0; k < BK; k++){
            float4 a4 = *(const float4*)&As[k][ty*4];
            float4 b4 = *(const float4*)&Bs[k][tx*4];
            float av[4] = {a4.x,a4.y,a4.z,a4.w};
            float bv[4] = {b4.x,b4.y,b4.z,b4.w};
            #pragma unroll
            for (int i=0;i<4;i++)
                #pragma unroll
                for (int j=0;j<4;j++)
                    acc[i][j] = fmaf(av[i], bv[j], acc[i][j]);
        }
        __syncthreads();
    }
    #pragma unroll
    for (int i=0;i<4;i++){
        int m = m0 + ty*4 + i;
        #pragma unroll
        for (int j=0;j<4;j++){
            int n = n0 + tx*4 + j;
            float v = acc[i][j];
            if (n < Hh) g_hp[m*Hh + n] = v + bp[n];
            else        g_ha[m*(Cc*Hh) + (n-Hh)] = v + ba[n-Hh];
        }
    }
}

// ---------------------------------------------------------------------------
// Kernel B: biaffine  out[b,p,c,a] = sum_h Wout[c,h]*tanh(hp[b,p,h]+ha[b,a,c,h])
//           + mask add (NEG where not masked-in)
// ---------------------------------------------------------------------------
#define TP 16
#define TA 16
#define HC 32

__global__ __launch_bounds__(256) void k_biaffine(const int* __restrict__ att,
        const void* __restrict__ ng, const float* __restrict__ Wout){
    __shared__ float s_hp[TP][HC+1];
    __shared__ float s_ha[Cc][HC][TA+1];
    __shared__ float s_w[Cc][HC];
    int bx = blockIdx.x;
    int b   = bx >> 6;
    int rem = bx & 63;
    int p0 = (rem >> 3) * TP;
    int a0 = (rem & 7)  * TA;
    int tid = threadIdx.x;
    int p = tid >> 4, a = tid & 15;
    float acc[Cc] = {};
    for (int h0 = 0; h0 < Hh; h0 += HC){
        #pragma unroll
        for (int i=0;i<2;i++){
            int idx = tid + i*256;
            int pl = idx >> 5, j = idx & 31;
            s_hp[pl][j] = g_hp[(b*Ss + p0 + pl)*Hh + h0 + j];
        }
        #pragma unroll
        for (int i=0;i<10;i++){
            int idx = tid + i*256;
            int al = idx / (Cc*HC);
            int r  = idx % (Cc*HC);
            int c  = r / HC;
            int j  = r % HC;
            s_ha[c][j][al] = g_ha[((b*Ss + a0 + al)*Cc + c)*Hh + h0 + j];
        }
        if (tid < Cc*HC){
            int c = tid / HC, j = tid % HC;
            s_w[c][j] = Wout[c*Hh + h0 + j];
        }
        __syncthreads();
        #pragma unroll 4
        for (int j=0;j<HC;j++){
            float hpv = s_hp[p][j];
            #pragma unroll
            for (int c=0;c<Cc;c++){
                float t = tanh_fast(hpv + s_ha[c][j][a]);
                acc[c] = fmaf(t, s_w[c][j], acc[c]);
            }
        }
        __syncthreads();
    }
    int pg = p0 + p, ag = a0 + a;
    int mode = g_ngMode;
    bool attv = att[b*Ss + ag] > 0;
    bool m = false;
    #pragma unroll
    for (int c=0;c<Cc;c++)
        m = m || ng_bit(ng, ((b*Ss+pg)*Cc + c)*Ss + ag, mode);
    float add = (m && attv) ? 0.0f : NEGV;
    #pragma unroll
    for (int c=0;c<Cc;c++)
        g_out[((b*Ss+pg)*Cc + c)*Ss + ag] = acc[c] + add;
}

// ---------------------------------------------------------------------------
// Kernel C: per-row (b,p,c) log-softmax over a (128) + CE partials.
// ---------------------------------------------------------------------------
__global__ __launch_bounds__(128) void k_rowloss(const float* __restrict__ target){
    int row = blockIdx.x;
    int t = threadIdx.x;
    const unsigned FULL = 0xffffffffu;
    __shared__ float sa[4], sb[4];
    int w = t >> 5, l = t & 31;

    float v = g_out[row*Ss + t];
    float m = v;
    #pragma unroll
    for (int o=16;o>0;o>>=1) m = fmaxf(m, __shfl_xor_sync(FULL,m,o));
    if (l==0) sa[w] = m;
    __syncthreads();
    m = fmaxf(fmaxf(sa[0],sa[1]), fmaxf(sa[2],sa[3]));

    float e = __expf(v - m);
    float s = e;
    #pragma unroll
    for (int o=16;o>0;o>>=1) s += __shfl_xor_sync(FULL,s,o);
    if (l==0) sb[w] = s;
    __syncthreads();
    s = sb[0]+sb[1]+sb[2]+sb[3];
    float logZ = __logf(s) + m;

    float tg = target[row*Ss + t];
    float num = tg * (logZ - v);
    float den = tg;
    #pragma unroll
    for (int o=16;o>0;o>>=1){
        num += __shfl_xor_sync(FULL,num,o);
        den += __shfl_xor_sync(FULL,den,o);
    }
    __syncthreads();
    if (l==0){ sa[w]=num; sb[w]=den; }
    __syncthreads();
    if (t==0){
        g_rnum[row] = sa[0]+sa[1]+sa[2]+sa[3];
        g_rden[row] = sb[0]+sb[1]+sb[2]+sb[3];
    }
}

__global__ __launch_bounds__(256) void k_finalize(float* out, int writeLoss){
    int t = threadIdx.x;
    float n=0.f, d=0.f;
    for (int i=t; i<NROWS; i+=256){ n += g_rnum[i]; d += g_rden[i]; }
    __shared__ float sn[256], sd[256];
    sn[t]=n; sd[t]=d; __syncthreads();
    for (int o=128;o>0;o>>=1){
        if (t<o){ sn[t]+=sn[t+o]; sd[t]+=sd[t+o]; }
        __syncthreads();
    }
    if (t==0 && writeLoss) out[0] = sn[0]/sd[0];
}

__global__ __launch_bounds__(256) void k_copy(float* __restrict__ dst){
    int i = blockIdx.x*256 + threadIdx.x;
    if (i < OUTN) dst[i] = g_out[i];
}

// ---------------------------------------------------------------------------
extern "C" void kernel_launch(void* const* d_in, const int* in_sizes, int n_in,
                              void* d_out, int out_size){
    const float*         seq  = (const float*)d_in[0];
    const int*           att  = (const int*)d_in[1];
    const unsigned char* ng   = (const unsigned char*)d_in[2];
    const float*         targ = (const float*)d_in[3];
    const float*         Wp   = (const float*)d_in[4];
    const float*         bp   = (const float*)d_in[5];
    const float*         Wa   = (const float*)d_in[6];
    const float*         ba   = (const float*)d_in[7];
    const float*         Wout = (const float*)d_in[8];
    float* out = (float*)d_out;

    k_detect<<<1, 256>>>(ng);

    dim3 g1(NTOT/BN, Mm/BM);
    k_gemm<<<g1, 256>>>(seq, Wp, bp, Wa, ba);
    k_biaffine<<<Bb*(Ss/TP)*(Ss/TA), 256>>>(att, (const void*)ng, Wout);

    int wantLoss = (out_size != OUTN) ? 1 : 0;
    int wantOut  = (out_size >= OUTN) ? 1 : 0;
    if (wantLoss){
        k_rowloss<<<NROWS, 128>>>(targ);
        k_finalize<<<1, 256>>>(out, 1);
    }
    if (wantOut){
        float* dst = out + ((out_size > OUTN) ? 1 : 0);
        k_copy<<<(OUTN+255)/256, 256>>>(dst);
    }
}

// round 3
// speedup vs baseline: 1.3123x; 1.3123x over previous
#include <cuda_runtime.h>
#include <cuda_bf16.h>
#include <math.h>

#define Bb 2
#define Ss 128
#define Hh 768
#define Cc 5
#define NEGV (-1024.0f)
#define Mm (Bb*Ss)          // 256
#define NTOT (Hh + Cc*Hh)   // 4608
#define NROWS (Bb*Ss*Cc)    // 1280
#define OUTN (Bb*Ss*Cc*Ss)  // 163840

#define KG  (Hh/16)         // 48 k16-groups
#define MI  (Mm/16)         // 16 m16-tiles
#define NI8 (NTOT/8)        // 576 n8-tiles

__device__ float g_hp[Mm*Hh];
__device__ float g_ha[Mm*Cc*Hh];
__device__ float g_out[OUTN];
__device__ float g_rnum[NROWS];
__device__ float g_rden[NROWS];
__device__ float g_maskadd[Bb*Ss*Ss];
__device__ int   g_ngMode;                       // 0=u8 1=i32 2=f32
__device__ unsigned int g_Af[KG*MI*32*4];        // A fragments (bf16x2 words)
__device__ unsigned int g_Bf[KG*NI8*32*2];       // B fragments

__device__ __forceinline__ float tanh_fast(float x){
    float y; asm("tanh.approx.f32 %0, %1;" : "=f"(y) : "f"(x)); return y;
}
__device__ __forceinline__ unsigned pack_bf2(float lo, float hi){
    __nv_bfloat162 v = __floats2bfloat162_rn(lo, hi);
    return *reinterpret_cast<unsigned*>(&v);
}

// ---------------------------------------------------------------------------
// detect ng_token_mask storage dtype
// ---------------------------------------------------------------------------
__global__ __launch_bounds__(256) void k_detect(const unsigned char* __restrict__ ng){
    __shared__ int s_b1, s_f3;
    if (threadIdx.x == 0){ s_b1 = 0; s_f3 = 0; }
    __syncthreads();
    int b1 = 0, f3 = 0;
    for (int i = threadIdx.x; i < 16384; i += 256){
        unsigned char v = ng[i];
        int o = i & 3;
        if (o == 1 && v) b1 = 1;
        if (o == 3 && v == 0x3F) f3 = 1;
    }
    if (b1) s_b1 = 1;
    if (f3) s_f3 = 1;
    __syncthreads();
    if (threadIdx.x == 0) g_ngMode = s_b1 ? 0 : (s_f3 ? 2 : 1);
}

__device__ __forceinline__ bool ng_bit(const void* ng, int idx, int mode){
    if (mode == 1) return ((const int*)ng)[idx] != 0;
    if (mode == 2) return ((const float*)ng)[idx] != 0.0f;
    return ((const unsigned char*)ng)[idx] != 0;
}

// ---------------------------------------------------------------------------
// prep: build bf16 mma fragment buffers (per-lane order) + mask-add table
//   A word w: reg=w&3, lane=(w>>2)&31, mi=(w>>7)%MI, g=(w>>7)/MI
//     m = mi*16 + (lane>>2) + (reg&1)*8 ; k = g*16 + (lane&3)*2 + (reg>>1)*8
//   B word w: reg=w&1, lane=(w>>1)&31, ni=(w>>6)%NI8, g=(w>>6)/NI8
//     n = ni*8 + (lane>>2)            ; k = g*16 + (lane&3)*2 + reg*8
// ---------------------------------------------------------------------------
#define AW (KG*MI*32*4)      // 98304
#define BW (KG*NI8*32*2)     // 1769472
#define MW (Bb*Ss*Ss)        // 32768
#define PREPTOT (AW+BW+MW)   // 1900544

__global__ __launch_bounds__(256) void k_prep(const float* __restrict__ X,
        const float* __restrict__ Wp, const float* __restrict__ Wa,
        const int* __restrict__ att, const void* __restrict__ ng){
    int idx = blockIdx.x*256 + threadIdx.x;
    if (idx < AW){
        int w = idx;
        int reg = w & 3, lane = (w>>2)&31;
        int mi = (w>>7) % MI, g = (w>>7) / MI;
        int m = mi*16 + (lane>>2) + (reg&1)*8;
        int k = g*16 + (lane&3)*2 + (reg>>1)*8;
        float2 v = *(const float2*)&X[m*Hh + k];
        g_Af[w] = pack_bf2(v.x, v.y);
    } else if (idx < AW + BW){
        int w = idx - AW;
        int reg = w & 1, lane = (w>>1)&31;
        int ni = (w>>6) % NI8, g = (w>>6) / NI8;
        int n = ni*8 + (lane>>2);
        int k = g*16 + (lane&3)*2 + reg*8;
        float2 v = (n < Hh) ? *(const float2*)&Wp[n*Hh + k]
                            : *(const float2*)&Wa[(n-Hh)*Hh + k];
        g_Bf[w] = pack_bf2(v.x, v.y);
    } else if (idx < PREPTOT){
        int w = idx - AW - BW;          // b*16384 + p*128 + a
        int a = w & 127;
        int bp_ = w >> 7;               // b*128 + p
        int b = bp_ >> 7;
        int mode = g_ngMode;
        bool attv = att[b*Ss + a] > 0;
        bool m = false;
        #pragma unroll
        for (int c = 0; c < Cc; c++)
            m = m || ng_bit(ng, (bp_*Cc + c)*Ss + a, mode);
        g_maskadd[w] = (m && attv) ? 0.0f : NEGV;
    }
}

// ---------------------------------------------------------------------------
// GEMM via mma.sync m16n8k16 bf16, fragments pre-staged in g_Af/g_Bf.
// CTA tile 128(M) x 64(N); 8 warps = 2(M) x 4(N); warp tile 64x16.
// grid = (72, 2)
// ---------------------------------------------------------------------------
__device__ __forceinline__ void mma_bf16(float& d0, float& d1, float& d2, float& d3,
        unsigned a0, unsigned a1, unsigned a2, unsigned a3,
        unsigned b0, unsigned b1){
    asm volatile("mma.sync.aligned.m16n8k16.row.col.f32.bf16.bf16.f32 "
        "{%0,%1,%2,%3}, {%4,%5,%6,%7}, {%8,%9}, {%0,%1,%2,%3};"
        : "+f"(d0), "+f"(d1), "+f"(d2), "+f"(d3)
        : "r"(a0), "r"(a1), "r"(a2), "r"(a3), "r"(b0), "r"(b1));
}

__global__ __launch_bounds__(256) void k_gemm(const float* __restrict__ bp,
                                              const float* __restrict__ ba){
    int tid = threadIdx.x;
    int wid = tid >> 5, lane = tid & 31;
    int wr = wid >> 2, wc = wid & 3;
    int mi0 = blockIdx.y*8 + wr*4;        // 4 consecutive m16 tiles
    int ni0 = blockIdx.x*8 + wc*2;        // 2 consecutive n8 tiles

    float acc[4][2][4];
    #pragma unroll
    for (int i=0;i<4;i++) for (int j=0;j<2;j++) for (int q=0;q<4;q++) acc[i][j][q]=0.f;

    const uint4* pA = reinterpret_cast<const uint4*>(g_Af);
    const uint2* pB = reinterpret_cast<const uint2*>(g_Bf);

    uint4 Ac[4]; uint2 Bc[2];
    #pragma unroll
    for (int mf=0; mf<4; mf++) Ac[mf] = pA[((0*MI + mi0+mf)*32) + lane + mf*0];
    #pragma unroll
    for (int mf=0; mf<4; mf++) Ac[mf] = pA[((0*MI + mi0+mf)*32) + lane];
    #pragma unroll
    for (int nf=0; nf<2; nf++) Bc[nf] = pB[((0*NI8 + ni0+nf)*32) + lane];

    for (int g = 0; g < KG; g++){
        uint4 An[4]; uint2 Bn[2];
        if (g+1 < KG){
            #pragma unroll
            for (int mf=0; mf<4; mf++) An[mf] = pA[(((g+1)*MI + mi0+mf)*32) + lane];
            #pragma unroll
            for (int nf=0; nf<2; nf++) Bn[nf] = pB[(((g+1)*NI8 + ni0+nf)*32) + lane];
        }
        #pragma unroll
        for (int mf=0; mf<4; mf++)
            #pragma unroll
            for (int nf=0; nf<2; nf++)
                mma_bf16(acc[mf][nf][0], acc[mf][nf][1], acc[mf][nf][2], acc[mf][nf][3],
                         Ac[mf].x, Ac[mf].y, Ac[mf].z, Ac[mf].w, Bc[nf].x, Bc[nf].y);
        if (g+1 < KG){
            #pragma unroll
            for (int mf=0; mf<4; mf++) Ac[mf] = An[mf];
            #pragma unroll
            for (int nf=0; nf<2; nf++) Bc[nf] = Bn[nf];
        }
    }

    // epilogue: bias add + scatter to g_hp / g_ha
    int r = lane >> 2, c2 = (lane & 3)*2;
    #pragma unroll
    for (int nf=0; nf<2; nf++){
        int n = (ni0+nf)*8 + c2;
        float2 bias = (n < Hh) ? *(const float2*)&bp[n] : *(const float2*)&ba[n-Hh];
        #pragma unroll
        for (int mf=0; mf<4; mf++){
            int m1 = (mi0+mf)*16 + r;
            int m2 = m1 + 8;
            float2 v1 = { acc[mf][nf][0] + bias.x, acc[mf][nf][1] + bias.y };
            float2 v2 = { acc[mf][nf][2] + bias.x, acc[mf][nf][3] + bias.y };
            if (n < Hh){
                *(float2*)&g_hp[m1*Hh + n] = v1;
                *(float2*)&g_hp[m2*Hh + n] = v2;
            } else {
                *(float2*)&g_ha[m1*(Cc*Hh) + (n-Hh)] = v1;
                *(float2*)&g_ha[m2*(Cc*Hh) + (n-Hh)] = v2;
            }
        }
    }
}

// ---------------------------------------------------------------------------
// biaffine: out[b,p,c,a] = sum_h Wout[c,h]*tanh(hp[b,p,h]+ha[b,a,c,h]) + maskadd
// ---------------------------------------------------------------------------
#define TP 16
#define TA 16
#define HC 64

__global__ __launch_bounds__(256) void k_biaffine(const float* __restrict__ Wout){
    __shared__ float s_hp[TP][HC+1];
    __shared__ float s_ha[Cc][HC][TA+1];
    __shared__ float s_w[Cc][HC];
    int bx = blockIdx.x;
    int b   = bx >> 6;
    int rem = bx & 63;
    int p0 = (rem >> 3) * TP;
    int a0 = (rem & 7)  * TA;
    int tid = threadIdx.x;
    int p = tid >> 4, a = tid & 15;
    float acc[Cc] = {};
    for (int h0 = 0; h0 < Hh; h0 += HC){
        #pragma unroll
        for (int i=0;i<4;i++){
            int idx = tid + i*256;
            int pl = idx >> 6, j = idx & 63;
            s_hp[pl][j] = g_hp[(b*Ss + p0 + pl)*Hh + h0 + j];
        }
        #pragma unroll
        for (int i=0;i<20;i++){
            int idx = tid + i*256;
            int al = idx / (Cc*HC);
            int rr = idx % (Cc*HC);
            int c  = rr / HC;
            int j  = rr % HC;
            s_ha[c][j][al] = g_ha[((b*Ss + a0 + al)*Cc + c)*Hh + h0 + j];
        }
        if (tid < Cc*HC){
            int c = tid / HC, j = tid % HC;
            s_w[c][j] = Wout[c*Hh + h0 + j];
        }
        __syncthreads();
        #pragma unroll 4
        for (int j=0;j<HC;j++){
            float hpv = s_hp[p][j];
            #pragma unroll
            for (int c=0;c<Cc;c++){
                float t = tanh_fast(hpv + s_ha[c][j][a]);
                acc[c] = fmaf(t, s_w[c][j], acc[c]);
            }
        }
        __syncthreads();
    }
    int pg = p0 + p, ag = a0 + a;
    float add = g_maskadd[(b*Ss + pg)*Ss + ag];
    #pragma unroll
    for (int c=0;c<Cc;c++)
        g_out[((b*Ss+pg)*Cc + c)*Ss + ag] = acc[c] + add;
}

// ---------------------------------------------------------------------------
// loss: warp-per-row log-softmax CE partials, then tree-reduce
// ---------------------------------------------------------------------------
__global__ __launch_bounds__(256) void k_rowloss(const float* __restrict__ target){
    const unsigned FULL = 0xffffffffu;
    int wid = threadIdx.x >> 5, lane = threadIdx.x & 31;
    int row = blockIdx.x*8 + wid;
    const float4 v4 = *(const float4*)&g_out[row*Ss + lane*4];
    float m = fmaxf(fmaxf(v4.x, v4.y), fmaxf(v4.z, v4.w));
    #pragma unroll
    for (int o=16;o>0;o>>=1) m = fmaxf(m, __shfl_xor_sync(FULL,m,o));
    float s = __expf(v4.x-m) + __expf(v4.y-m) + __expf(v4.z-m) + __expf(v4.w-m);
    #pragma unroll
    for (int o=16;o>0;o>>=1) s += __shfl_xor_sync(FULL,s,o);
    float logZ = __logf(s) + m;
    const float4 t4 = *(const float4*)&target[row*Ss + lane*4];
    float num = t4.x*(logZ-v4.x) + t4.y*(logZ-v4.y) + t4.z*(logZ-v4.z) + t4.w*(logZ-v4.w);
    float den = t4.x + t4.y + t4.z + t4.w;
    #pragma unroll
    for (int o=16;o>0;o>>=1){
        num += __shfl_xor_sync(FULL,num,o);
        den += __shfl_xor_sync(FULL,den,o);
    }
    if (lane == 0){ g_rnum[row] = num; g_rden[row] = den; }
}

__global__ __launch_bounds__(256) void k_finalize(float* out, int writeLoss){
    int t = threadIdx.x;
    float n=0.f, d=0.f;
    for (int i=t; i<NROWS; i+=256){ n += g_rnum[i]; d += g_rden[i]; }
    __shared__ float sn[256], sd[256];
    sn[t]=n; sd[t]=d; __syncthreads();
    for (int o=128;o>0;o>>=1){
        if (t<o){ sn[t]+=sn[t+o]; sd[t]+=sd[t+o]; }
        __syncthreads();
    }
    if (t==0 && writeLoss) out[0] = sn[0]/sd[0];
}

__global__ __launch_bounds__(256) void k_copy(float* __restrict__ dst){
    int i = blockIdx.x*256 + threadIdx.x;
    if (i < OUTN) dst[i] = g_out[i];
}

// ---------------------------------------------------------------------------
extern "C" void kernel_launch(void* const* d_in, const int* in_sizes, int n_in,
                              void* d_out, int out_size){
    const float*         seq  = (const float*)d_in[0];
    const int*           att  = (const int*)d_in[1];
    const unsigned char* ng   = (const unsigned char*)d_in[2];
    const float*         targ = (const float*)d_in[3];
    const float*         Wp   = (const float*)d_in[4];
    const float*         bp   = (const float*)d_in[5];
    const float*         Wa   = (const float*)d_in[6];
    const float*         ba   = (const float*)d_in[7];
    const float*         Wout = (const float*)d_in[8];
    float* out = (float*)d_out;

    k_detect<<<1, 256>>>(ng);
    k_prep<<<(PREPTOT+255)/256, 256>>>(seq, Wp, Wa, att, (const void*)ng);
    k_gemm<<<dim3(NTOT/64, Mm/128), 256>>>(bp, ba);
    k_biaffine<<<Bb*(Ss/TP)*(Ss/TA), 256>>>(Wout);

    int wantLoss = (out_size != OUTN) ? 1 : 0;
    int wantOut  = (out_size >= OUTN) ? 1 : 0;
    if (wantLoss){
        k_rowloss<<<NROWS/8, 256>>>(targ);
        k_finalize<<<1, 256>>>(out, 1);
    }
    if (wantOut){
        float* dst = out + ((out_size > OUTN) ? 1 : 0);
        k_copy<<<(OUTN+255)/256, 256>>>(dst);
    }
}

// round 6
// speedup vs baseline: 1.3459x; 1.0256x over previous
#include <cuda_runtime.h>
#include <cuda_bf16.h>
#include <math.h>

#define Bb 2
#define Ss 128
#define Hh 768
#define Cc 5
#define NEGV (-1024.0f)
#define Mm (Bb*Ss)          // 256
#define NTOT (Hh + Cc*Hh)   // 4608
#define NROWS (Bb*Ss*Cc)    // 1280
#define OUTN (Bb*Ss*Cc*Ss)  // 163840

#define KG  (Hh/16)         // 48 k16-groups
#define MI  (Mm/16)         // 16 m16-tiles
#define NI8 (NTOT/8)        // 576 n8-tiles

__device__ float g_hp[Mm*Hh];
__device__ float g_ha[Mm*Cc*Hh];
__device__ float g_part[4*OUTN];
__device__ float g_out[OUTN];
__device__ float g_rnum[NROWS];
__device__ float g_rden[NROWS];
__device__ float g_maskadd[Bb*Ss*Ss];
__device__ int   g_ngMode;                    // 0=u8 1=i32 2=f32
__device__ unsigned g_Afh[KG*MI*32*4];        // A hi fragments (bf16x2 words)
__device__ unsigned g_Afl[KG*MI*32*4];        // A lo fragments
__device__ unsigned g_Bfh[KG*NI8*32*2];       // B hi fragments
__device__ unsigned g_Bfl[KG*NI8*32*2];       // B lo fragments

__device__ __forceinline__ float tanh_fast(float x){
    float y; asm("tanh.approx.f32 %0, %1;" : "=f"(y) : "f"(x)); return y;
}
__device__ __forceinline__ unsigned pack2(__nv_bfloat16 lo, __nv_bfloat16 hi){
    __nv_bfloat162 v; v.x = lo; v.y = hi;
    return *reinterpret_cast<unsigned*>(&v);
}
__device__ __forceinline__ void split_bf(float x, __nv_bfloat16& h, __nv_bfloat16& l){
    h = __float2bfloat16(x);
    l = __float2bfloat16(x - __bfloat162float(h));
}

// ---------------------------------------------------------------------------
// detect ng_token_mask storage dtype
// ---------------------------------------------------------------------------
__global__ __launch_bounds__(256) void k_detect(const unsigned char* __restrict__ ng){
    __shared__ int s_b1, s_f3;
    if (threadIdx.x == 0){ s_b1 = 0; s_f3 = 0; }
    __syncthreads();
    int b1 = 0, f3 = 0;
    for (int i = threadIdx.x; i < 16384; i += 256){
        unsigned char v = ng[i];
        int o = i & 3;
        if (o == 1 && v) b1 = 1;
        if (o == 3 && v == 0x3F) f3 = 1;
    }
    if (b1) s_b1 = 1;
    if (f3) s_f3 = 1;
    __syncthreads();
    if (threadIdx.x == 0) g_ngMode = s_b1 ? 0 : (s_f3 ? 2 : 1);
}

__device__ __forceinline__ bool ng_bit(const void* ng, int idx, int mode){
    if (mode == 1) return ((const int*)ng)[idx] != 0;
    if (mode == 2) return ((const float*)ng)[idx] != 0.0f;
    return ((const unsigned char*)ng)[idx] != 0;
}

// ---------------------------------------------------------------------------
// prep: bf16 hi/lo mma fragments (m16n8k16 per-lane order, proven in R3)
// ---------------------------------------------------------------------------
#define AW (KG*MI*32*4)      // 98304
#define BW (KG*NI8*32*2)     // 1769472
#define MW (Bb*Ss*Ss)        // 32768
#define PREPTOT (AW+BW+MW)

__global__ __launch_bounds__(256) void k_prep(const float* __restrict__ X,
        const float* __restrict__ Wp, const float* __restrict__ Wa,
        const int* __restrict__ att, const void* __restrict__ ng){
    int idx = blockIdx.x*256 + threadIdx.x;
    if (idx < AW){
        int w = idx;
        int reg = w & 3, lane = (w>>2)&31;
        int tile = w>>7;
        int mi = tile % MI, g = tile / MI;
        int m = mi*16 + (lane>>2) + (reg&1)*8;
        int k = g*16 + (lane&3)*2 + (reg>>1)*8;
        float2 v = *(const float2*)&X[m*Hh + k];
        __nv_bfloat16 hx,lx,hy,ly;
        split_bf(v.x, hx, lx); split_bf(v.y, hy, ly);
        g_Afh[w] = pack2(hx, hy);
        g_Afl[w] = pack2(lx, ly);
    } else if (idx < AW + BW){
        int w = idx - AW;
        int reg = w & 1, lane = (w>>1)&31;
        int tile = w>>6;
        int ni = tile % NI8, g = tile / NI8;
        int n = ni*8 + (lane>>2);
        int k = g*16 + (lane&3)*2 + reg*8;
        float2 v = (n < Hh) ? *(const float2*)&Wp[n*Hh + k]
                            : *(const float2*)&Wa[(n-Hh)*Hh + k];
        __nv_bfloat16 hx,lx,hy,ly;
        split_bf(v.x, hx, lx); split_bf(v.y, hy, ly);
        g_Bfh[w] = pack2(hx, hy);
        g_Bfl[w] = pack2(lx, ly);
    } else if (idx < PREPTOT){
        int w = idx - AW - BW;          // b*16384 + p*128 + a
        int a = w & 127;
        int bp_ = w >> 7;               // b*128 + p
        int b = bp_ >> 7;
        int mode = g_ngMode;
        bool attv = att[b*Ss + a] > 0;
        bool m = false;
        #pragma unroll
        for (int c = 0; c < Cc; c++)
            m = m || ng_bit(ng, (bp_*Cc + c)*Ss + a, mode);
        g_maskadd[w] = (m && attv) ? 0.0f : NEGV;
    }
}

// ---------------------------------------------------------------------------
// GEMM: mma m16n8k16 bf16, acc += Ah*Bh + Ah*Bl + Al*Bh
// ---------------------------------------------------------------------------
__device__ __forceinline__ void mma_bf16(float& d0, float& d1, float& d2, float& d3,
        unsigned a0, unsigned a1, unsigned a2, unsigned a3,
        unsigned b0, unsigned b1){
    asm volatile("mma.sync.aligned.m16n8k16.row.col.f32.bf16.bf16.f32 "
        "{%0,%1,%2,%3}, {%4,%5,%6,%7}, {%8,%9}, {%0,%1,%2,%3};"
        : "+f"(d0), "+f"(d1), "+f"(d2), "+f"(d3)
        : "r"(a0), "r"(a1), "r"(a2), "r"(a3), "r"(b0), "r"(b1));
}

__global__ __launch_bounds__(256) void k_gemm(const float* __restrict__ bp,
                                              const float* __restrict__ ba){
    int tid = threadIdx.x;
    int wid = tid >> 5, lane = tid & 31;
    int wr = wid >> 2, wc = wid & 3;
    int mi0 = blockIdx.y*8 + wr*4;
    int ni0 = blockIdx.x*8 + wc*2;

    float acc[4][2][4];
    #pragma unroll
    for (int i=0;i<4;i++) for (int j=0;j<2;j++) for (int q=0;q<4;q++) acc[i][j][q]=0.f;

    const uint4* pAh = reinterpret_cast<const uint4*>(g_Afh);
    const uint4* pAl = reinterpret_cast<const uint4*>(g_Afl);
    const uint2* pBh = reinterpret_cast<const uint2*>(g_Bfh);
    const uint2* pBl = reinterpret_cast<const uint2*>(g_Bfl);

    for (int g = 0; g < KG; g++){
        uint4 Ah[4], Al[4]; uint2 Bh[2], Bl[2];
        #pragma unroll
        for (int mf=0; mf<4; mf++){
            int t = (g*MI + mi0+mf)*32 + lane;
            Ah[mf] = pAh[t]; Al[mf] = pAl[t];
        }
        #pragma unroll
        for (int nf=0; nf<2; nf++){
            int t = (g*NI8 + ni0+nf)*32 + lane;
            Bh[nf] = pBh[t]; Bl[nf] = pBl[t];
        }
        #pragma unroll
        for (int mf=0; mf<4; mf++)
            #pragma unroll
            for (int nf=0; nf<2; nf++){
                mma_bf16(acc[mf][nf][0], acc[mf][nf][1], acc[mf][nf][2], acc[mf][nf][3],
                         Ah[mf].x, Ah[mf].y, Ah[mf].z, Ah[mf].w, Bh[nf].x, Bh[nf].y);
                mma_bf16(acc[mf][nf][0], acc[mf][nf][1], acc[mf][nf][2], acc[mf][nf][3],
                         Ah[mf].x, Ah[mf].y, Ah[mf].z, Ah[mf].w, Bl[nf].x, Bl[nf].y);
                mma_bf16(acc[mf][nf][0], acc[mf][nf][1], acc[mf][nf][2], acc[mf][nf][3],
                         Al[mf].x, Al[mf].y, Al[mf].z, Al[mf].w, Bh[nf].x, Bh[nf].y);
            }
    }

    int r = lane >> 2, c2 = (lane & 3)*2;
    #pragma unroll
    for (int nf=0; nf<2; nf++){
        int n = (ni0+nf)*8 + c2;
        float2 bias = (n < Hh) ? *(const float2*)&bp[n] : *(const float2*)&ba[n-Hh];
        #pragma unroll
        for (int mf=0; mf<4; mf++){
            int m1 = (mi0+mf)*16 + r;
            int m2 = m1 + 8;
            float2 v1 = { acc[mf][nf][0] + bias.x, acc[mf][nf][1] + bias.y };
            float2 v2 = { acc[mf][nf][2] + bias.x, acc[mf][nf][3] + bias.y };
            if (n < Hh){
                *(float2*)&g_hp[m1*Hh + n] = v1;
                *(float2*)&g_hp[m2*Hh + n] = v2;
            } else {
                *(float2*)&g_ha[m1*(Cc*Hh) + (n-Hh)] = v1;
                *(float2*)&g_ha[m2*(Cc*Hh) + (n-Hh)] = v2;
            }
        }
    }
}

// ---------------------------------------------------------------------------
// biaffine partial: 4-way h-split. BUGFIX: s_w load is now strided
// (Cc*HC=320 > 256 threads — previous single-shot guard left s_w[4][*] unset).
// ---------------------------------------------------------------------------
#define TP 16
#define TA 16
#define HC 64
#define HSEG 192

__global__ __launch_bounds__(256,4) void k_biaffine(const float* __restrict__ Wout){
    __shared__ float s_hp[TP][HC+1];
    __shared__ float s_ha[Cc][HC][TA+1];
    __shared__ float s_w[Cc][HC];
    int bx = blockIdx.x;
    int seg = bx & 3;
    int rest = bx >> 2;              // 0..127
    int b   = rest >> 6;
    int rem = rest & 63;
    int p0 = (rem >> 3) * TP;
    int a0 = (rem & 7)  * TA;
    int tid = threadIdx.x;
    int p = tid >> 4, a = tid & 15;
    int hbase = seg * HSEG;
    float acc[Cc] = {};
    for (int hh = 0; hh < HSEG; hh += HC){
        int h0 = hbase + hh;
        #pragma unroll
        for (int i=0;i<4;i++){
            int idx = tid + i*256;
            int pl = idx >> 6, j = idx & 63;
            s_hp[pl][j] = g_hp[(b*Ss + p0 + pl)*Hh + h0 + j];
        }
        #pragma unroll
        for (int i=0;i<20;i++){
            int idx = tid + i*256;
            int al = idx / (Cc*HC);
            int rr = idx % (Cc*HC);
            int c  = rr / HC;
            int j  = rr % HC;
            s_ha[c][j][al] = g_ha[((b*Ss + a0 + al)*Cc + c)*Hh + h0 + j];
        }
        for (int idx = tid; idx < Cc*HC; idx += 256){   // FIX: strided (320>256)
            int c = idx / HC, j = idx % HC;
            s_w[c][j] = Wout[c*Hh + h0 + j];
        }
        __syncthreads();
        #pragma unroll 4
        for (int j=0;j<HC;j++){
            float hpv = s_hp[p][j];
            #pragma unroll
            for (int c=0;c<Cc;c++){
                float t = tanh_fast(hpv + s_ha[c][j][a]);
                acc[c] = fmaf(t, s_w[c][j], acc[c]);
            }
        }
        __syncthreads();
    }
    int pg = p0 + p, ag = a0 + a;
    #pragma unroll
    for (int c=0;c<Cc;c++)
        g_part[seg*OUTN + ((b*Ss+pg)*Cc + c)*Ss + ag] = acc[c];
}

// ---------------------------------------------------------------------------
// combine: sum 4 partials + maskadd -> g_out (and optionally dst)
// ---------------------------------------------------------------------------
__global__ __launch_bounds__(256) void k_combine(float* __restrict__ dst, int writeOut){
    int i = blockIdx.x*256 + threadIdx.x;
    if (i >= OUTN) return;
    float v = g_part[i] + g_part[OUTN+i] + g_part[2*OUTN+i] + g_part[3*OUTN+i];
    int a = i & 127;
    int bpc = i >> 7;
    int bp = bpc / Cc;
    v += g_maskadd[bp*Ss + a];
    g_out[i] = v;
    if (writeOut) dst[i] = v;
}

// ---------------------------------------------------------------------------
// loss: warp-per-row log-softmax CE partials, then tree-reduce
// ---------------------------------------------------------------------------
__global__ __launch_bounds__(256) void k_rowloss(const float* __restrict__ target){
    const unsigned FULL = 0xffffffffu;
    int wid = threadIdx.x >> 5, lane = threadIdx.x & 31;
    int row = blockIdx.x*8 + wid;
    const float4 v4 = *(const float4*)&g_out[row*Ss + lane*4];
    float m = fmaxf(fmaxf(v4.x, v4.y), fmaxf(v4.z, v4.w));
    #pragma unroll
    for (int o=16;o>0;o>>=1) m = fmaxf(m, __shfl_xor_sync(FULL,m,o));
    float s = __expf(v4.x-m) + __expf(v4.y-m) + __expf(v4.z-m) + __expf(v4.w-m);
    #pragma unroll
    for (int o=16;o>0;o>>=1) s += __shfl_xor_sync(FULL,s,o);
    float logZ = __logf(s) + m;
    const float4 t4 = *(const float4*)&target[row*Ss + lane*4];
    float num = t4.x*(logZ-v4.x) + t4.y*(logZ-v4.y) + t4.z*(logZ-v4.z) + t4.w*(logZ-v4.w);
    float den = t4.x + t4.y + t4.z + t4.w;
    #pragma unroll
    for (int o=16;o>0;o>>=1){
        num += __shfl_xor_sync(FULL,num,o);
        den += __shfl_xor_sync(FULL,den,o);
    }
    if (lane == 0){ g_rnum[row] = num; g_rden[row] = den; }
}

__global__ __launch_bounds__(256) void k_finalize(float* out){
    int t = threadIdx.x;
    float n=0.f, d=0.f;
    for (int i=t; i<NROWS; i+=256){ n += g_rnum[i]; d += g_rden[i]; }
    __shared__ float sn[256], sd[256];
    sn[t]=n; sd[t]=d; __syncthreads();
    for (int o=128;o>0;o>>=1){
        if (t<o){ sn[t]+=sn[t+o]; sd[t]+=sd[t+o]; }
        __syncthreads();
    }
    if (t==0) out[0] = sn[0]/sd[0];
}

// ---------------------------------------------------------------------------
extern "C" void kernel_launch(void* const* d_in, const int* in_sizes, int n_in,
                              void* d_out, int out_size){
    const float*         seq  = (const float*)d_in[0];
    const int*           att  = (const int*)d_in[1];
    const unsigned char* ng   = (const unsigned char*)d_in[2];
    const float*         targ = (const float*)d_in[3];
    const float*         Wp   = (const float*)d_in[4];
    const float*         bp   = (const float*)d_in[5];
    const float*         Wa   = (const float*)d_in[6];
    const float*         ba   = (const float*)d_in[7];
    const float*         Wout = (const float*)d_in[8];
    float* out = (float*)d_out;

    k_detect<<<1, 256>>>(ng);
    k_prep<<<(PREPTOT+255)/256, 256>>>(seq, Wp, Wa, att, (const void*)ng);
    k_gemm<<<dim3(NTOT/64, Mm/128), 256>>>(bp, ba);
    k_biaffine<<<512, 256>>>(Wout);

    int wantLoss = (out_size != OUTN) ? 1 : 0;
    int wantOut  = (out_size >= OUTN) ? 1 : 0;
    float* dst = out + ((out_size > OUTN) ? 1 : 0);
    k_combine<<<(OUTN+255)/256, 256>>>(dst, wantOut);
    if (wantLoss){
        k_rowloss<<<NROWS/8, 256>>>(targ);
        k_finalize<<<1, 256>>>(out);
    }
}

// round 7
// speedup vs baseline: 1.7576x; 1.3059x over previous
#include <cuda_runtime.h>
#include <cuda_bf16.h>
#include <cuda_fp16.h>
#include <math.h>

#define Bb 2
#define Ss 128
#define Hh 768
#define Cc 5
#define NEGV (-1024.0f)
#define Mm (Bb*Ss)          // 256
#define NTOT (Hh + Cc*Hh)   // 4608
#define NROWS (Bb*Ss*Cc)    // 1280
#define OUTN (Bb*Ss*Cc*Ss)  // 163840

#define KG  (Hh/16)         // 48
#define MI  (Mm/16)         // 16
#define NI8 (NTOT/8)        // 576

__device__ float g_hp[Mm*Hh];
__device__ float g_ha[Mm*Cc*Hh];
__device__ float g_part[4*OUTN];
__device__ float g_rnum[NROWS];
__device__ float g_rden[NROWS];
__device__ float g_maskadd[Bb*Ss*Ss];
__device__ int   g_ngMode;
__device__ unsigned g_Afh[KG*MI*32*4];
__device__ unsigned g_Afl[KG*MI*32*4];
__device__ unsigned g_Bfh[KG*NI8*32*2];
__device__ unsigned g_Bfl[KG*NI8*32*2];

__device__ __forceinline__ unsigned pack2(__nv_bfloat16 lo, __nv_bfloat16 hi){
    __nv_bfloat162 v; v.x = lo; v.y = hi;
    return *reinterpret_cast<unsigned*>(&v);
}
__device__ __forceinline__ void split_bf(float x, __nv_bfloat16& h, __nv_bfloat16& l){
    h = __float2bfloat16(x);
    l = __float2bfloat16(x - __bfloat162float(h));
}

// ---------------------------------------------------------------------------
__global__ __launch_bounds__(256) void k_detect(const unsigned char* __restrict__ ng){
    __shared__ int s_b1, s_f3;
    if (threadIdx.x == 0){ s_b1 = 0; s_f3 = 0; }
    __syncthreads();
    int b1 = 0, f3 = 0;
    for (int i = threadIdx.x; i < 16384; i += 256){
        unsigned char v = ng[i];
        int o = i & 3;
        if (o == 1 && v) b1 = 1;
        if (o == 3 && v == 0x3F) f3 = 1;
    }
    if (b1) s_b1 = 1;
    if (f3) s_f3 = 1;
    __syncthreads();
    if (threadIdx.x == 0) g_ngMode = s_b1 ? 0 : (s_f3 ? 2 : 1);
}

__device__ __forceinline__ bool ng_bit(const void* ng, int idx, int mode){
    if (mode == 1) return ((const int*)ng)[idx] != 0;
    if (mode == 2) return ((const float*)ng)[idx] != 0.0f;
    return ((const unsigned char*)ng)[idx] != 0;
}

// ---------------------------------------------------------------------------
#define AW (KG*MI*32*4)
#define BW (KG*NI8*32*2)
#define MW (Bb*Ss*Ss)
#define PREPTOT (AW+BW+MW)

__global__ __launch_bounds__(256) void k_prep(const float* __restrict__ X,
        const float* __restrict__ Wp, const float* __restrict__ Wa,
        const int* __restrict__ att, const void* __restrict__ ng){
    int idx = blockIdx.x*256 + threadIdx.x;
    if (idx < AW){
        int w = idx;
        int reg = w & 3, lane = (w>>2)&31;
        int tile = w>>7;
        int mi = tile % MI, g = tile / MI;
        int m = mi*16 + (lane>>2) + (reg&1)*8;
        int k = g*16 + (lane&3)*2 + (reg>>1)*8;
        float2 v = *(const float2*)&X[m*Hh + k];
        __nv_bfloat16 hx,lx,hy,ly;
        split_bf(v.x, hx, lx); split_bf(v.y, hy, ly);
        g_Afh[w] = pack2(hx, hy);
        g_Afl[w] = pack2(lx, ly);
    } else if (idx < AW + BW){
        int w = idx - AW;
        int reg = w & 1, lane = (w>>1)&31;
        int tile = w>>6;
        int ni = tile % NI8, g = tile / NI8;
        int n = ni*8 + (lane>>2);
        int k = g*16 + (lane&3)*2 + reg*8;
        float2 v = (n < Hh) ? *(const float2*)&Wp[n*Hh + k]
                            : *(const float2*)&Wa[(n-Hh)*Hh + k];
        __nv_bfloat16 hx,lx,hy,ly;
        split_bf(v.x, hx, lx); split_bf(v.y, hy, ly);
        g_Bfh[w] = pack2(hx, hy);
        g_Bfl[w] = pack2(lx, ly);
    } else if (idx < PREPTOT){
        int w = idx - AW - BW;
        int a = w & 127;
        int bp_ = w >> 7;
        int b = bp_ >> 7;
        int mode = g_ngMode;
        bool attv = att[b*Ss + a] > 0;
        bool m = false;
        #pragma unroll
        for (int c = 0; c < Cc; c++)
            m = m || ng_bit(ng, (bp_*Cc + c)*Ss + a, mode);
        g_maskadd[w] = (m && attv) ? 0.0f : NEGV;
    }
}

// ---------------------------------------------------------------------------
// GEMM: mma m16n8k16 bf16, acc += Ah*Bh + Ah*Bl + Al*Bh, double-buffered
// ---------------------------------------------------------------------------
__device__ __forceinline__ void mma_bf16(float& d0, float& d1, float& d2, float& d3,
        unsigned a0, unsigned a1, unsigned a2, unsigned a3,
        unsigned b0, unsigned b1){
    asm volatile("mma.sync.aligned.m16n8k16.row.col.f32.bf16.bf16.f32 "
        "{%0,%1,%2,%3}, {%4,%5,%6,%7}, {%8,%9}, {%0,%1,%2,%3};"
        : "+f"(d0), "+f"(d1), "+f"(d2), "+f"(d3)
        : "r"(a0), "r"(a1), "r"(a2), "r"(a3), "r"(b0), "r"(b1));
}

__global__ __launch_bounds__(256) void k_gemm(const float* __restrict__ bp,
                                              const float* __restrict__ ba){
    int tid = threadIdx.x;
    int wid = tid >> 5, lane = tid & 31;
    int wr = wid >> 2, wc = wid & 3;
    int mi0 = blockIdx.y*8 + wr*4;
    int ni0 = blockIdx.x*8 + wc*2;

    float acc[4][2][4];
    #pragma unroll
    for (int i=0;i<4;i++) for (int j=0;j<2;j++) for (int q=0;q<4;q++) acc[i][j][q]=0.f;

    const uint4* pAh = reinterpret_cast<const uint4*>(g_Afh);
    const uint4* pAl = reinterpret_cast<const uint4*>(g_Afl);
    const uint2* pBh = reinterpret_cast<const uint2*>(g_Bfh);
    const uint2* pBl = reinterpret_cast<const uint2*>(g_Bfl);

    uint4 Ah[4], Al[4]; uint2 Bh[2], Bl[2];
    #pragma unroll
    for (int mf=0; mf<4; mf++){
        int t = (0*MI + mi0+mf)*32 + lane;
        Ah[mf] = pAh[t]; Al[mf] = pAl[t];
    }
    #pragma unroll
    for (int nf=0; nf<2; nf++){
        int t = (0*NI8 + ni0+nf)*32 + lane;
        Bh[nf] = pBh[t]; Bl[nf] = pBl[t];
    }

    for (int g = 0; g < KG; g++){
        uint4 An[4], Aln[4]; uint2 Bn[2], Bln[2];
        if (g+1 < KG){
            #pragma unroll
            for (int mf=0; mf<4; mf++){
                int t = ((g+1)*MI + mi0+mf)*32 + lane;
                An[mf] = pAh[t]; Aln[mf] = pAl[t];
            }
            #pragma unroll
            for (int nf=0; nf<2; nf++){
                int t = ((g+1)*NI8 + ni0+nf)*32 + lane;
                Bn[nf] = pBh[t]; Bln[nf] = pBl[t];
            }
        }
        #pragma unroll
        for (int mf=0; mf<4; mf++)
            #pragma unroll
            for (int nf=0; nf<2; nf++){
                mma_bf16(acc[mf][nf][0], acc[mf][nf][1], acc[mf][nf][2], acc[mf][nf][3],
                         Ah[mf].x, Ah[mf].y, Ah[mf].z, Ah[mf].w, Bh[nf].x, Bh[nf].y);
                mma_bf16(acc[mf][nf][0], acc[mf][nf][1], acc[mf][nf][2], acc[mf][nf][3],
                         Ah[mf].x, Ah[mf].y, Ah[mf].z, Ah[mf].w, Bl[nf].x, Bl[nf].y);
                mma_bf16(acc[mf][nf][0], acc[mf][nf][1], acc[mf][nf][2], acc[mf][nf][3],
                         Al[mf].x, Al[mf].y, Al[mf].z, Al[mf].w, Bh[nf].x, Bh[nf].y);
            }
        if (g+1 < KG){
            #pragma unroll
            for (int mf=0; mf<4; mf++){ Ah[mf]=An[mf]; Al[mf]=Aln[mf]; }
            #pragma unroll
            for (int nf=0; nf<2; nf++){ Bh[nf]=Bn[nf]; Bl[nf]=Bln[nf]; }
        }
    }

    int r = lane >> 2, c2 = (lane & 3)*2;
    #pragma unroll
    for (int nf=0; nf<2; nf++){
        int n = (ni0+nf)*8 + c2;
        float2 bias = (n < Hh) ? *(const float2*)&bp[n] : *(const float2*)&ba[n-Hh];
        #pragma unroll
        for (int mf=0; mf<4; mf++){
            int m1 = (mi0+mf)*16 + r;
            int m2 = m1 + 8;
            float2 v1 = { acc[mf][nf][0] + bias.x, acc[mf][nf][1] + bias.y };
            float2 v2 = { acc[mf][nf][2] + bias.x, acc[mf][nf][3] + bias.y };
            if (n < Hh){
                *(float2*)&g_hp[m1*Hh + n] = v1;
                *(float2*)&g_hp[m2*Hh + n] = v2;
            } else {
                *(float2*)&g_ha[m1*(Cc*Hh) + (n-Hh)] = v1;
                *(float2*)&g_ha[m2*(Cc*Hh) + (n-Hh)] = v2;
            }
        }
    }
}

// ---------------------------------------------------------------------------
// biaffine partial: f16x2 tanh, 128-thread CTAs (TP=16 x TA=8), 4-way h-split.
// grid = 1024: seg = bx&3; tile = bx>>2 (b x 8 ptiles x 16 atiles)
// ---------------------------------------------------------------------------
#define TP 16
#define TA 8
#define HC 64
#define HSEG 192
#define JP (HC/2)

__global__ __launch_bounds__(128,8) void k_biaffine(const float* __restrict__ Wout){
    __shared__ float s_hp[TP][HC+2];          // pair-contiguous, pad 2
    __shared__ float s_ha[Cc][JP][2*TA+2];    // [c][jp][2a+(j&1)], pad 2
    __shared__ float s_w[Cc][HC];             // pair-contiguous
    int bx = blockIdx.x;
    int seg  = bx & 3;
    int rest = bx >> 2;               // 0..255
    int b   = rest >> 7;
    int rem = rest & 127;
    int p0 = (rem >> 4) * TP;
    int a0 = (rem & 15) * TA;
    int tid = threadIdx.x;
    int p = tid >> 3, a = tid & 7;
    int hbase = seg * HSEG;

    float acc0[Cc] = {}, acc1[Cc] = {};
    for (int hh = 0; hh < HSEG; hh += HC){
        int h0 = hbase + hh;
        #pragma unroll
        for (int i=0;i<8;i++){
            int idx = tid + i*128;
            int pl = idx >> 6, j = idx & 63;
            s_hp[pl][j] = g_hp[(b*Ss + p0 + pl)*Hh + h0 + j];
        }
        #pragma unroll
        for (int i=0;i<20;i++){
            int idx = tid + i*128;
            int al = idx / (Cc*HC);
            int rr = idx % (Cc*HC);
            int c  = rr >> 6;
            int j  = rr & 63;
            s_ha[c][j>>1][2*al + (j&1)] =
                g_ha[((b*Ss + a0 + al)*Cc + c)*Hh + h0 + j];
        }
        for (int idx = tid; idx < Cc*HC; idx += 128){
            int c = idx >> 6, j = idx & 63;
            s_w[c][j] = Wout[c*Hh + h0 + j];
        }
        __syncthreads();
        #pragma unroll 2
        for (int jp=0;jp<JP;jp++){
            float2 hp2 = *(const float2*)&s_hp[p][2*jp];
            #pragma unroll
            for (int c=0;c<Cc;c++){
                float2 ha2 = *(const float2*)&s_ha[c][jp][2*a];
                float x0 = hp2.x + ha2.x;
                float x1 = hp2.y + ha2.y;
                unsigned h2, t2;
                asm("cvt.rn.f16x2.f32 %0, %1, %2;" : "=r"(h2) : "f"(x1), "f"(x0));
                asm("tanh.approx.f16x2 %0, %1;" : "=r"(t2) : "r"(h2));
                __half2 th = *reinterpret_cast<__half2*>(&t2);
                float2 w2 = *(const float2*)&s_w[c][2*jp];
                acc0[c] = fmaf(__low2float(th),  w2.x, acc0[c]);
                acc1[c] = fmaf(__high2float(th), w2.y, acc1[c]);
            }
        }
        __syncthreads();
    }
    int pg = p0 + p, ag = a0 + a;
    #pragma unroll
    for (int c=0;c<Cc;c++)
        g_part[seg*OUTN + ((b*Ss+pg)*Cc + c)*Ss + ag] = acc0[c] + acc1[c];
}

// ---------------------------------------------------------------------------
// combine + fused per-row log-softmax CE: block = 256 outputs = 2 rows of 128
// ---------------------------------------------------------------------------
__global__ __launch_bounds__(256) void k_combine(const float* __restrict__ targ,
        float* __restrict__ dst, int writeOut){
    const unsigned FULL = 0xffffffffu;
    int tid = threadIdx.x;
    int i = blockIdx.x*256 + tid;
    float v = g_part[i] + g_part[OUTN+i] + g_part[2*OUTN+i] + g_part[3*OUTN+i];
    int a = i & 127;
    int row = i >> 7;                 // (b*Ss+p)*Cc + c
    int bp = row / Cc;
    v += g_maskadd[bp*Ss + a];
    if (writeOut) dst[i] = v;

    int w = tid >> 5, lane = tid & 31, rg = tid >> 7;
    __shared__ float sA[8], sB[8];

    float m = v;
    #pragma unroll
    for (int o=16;o>0;o>>=1) m = fmaxf(m, __shfl_xor_sync(FULL,m,o));
    if (lane==0) sA[w] = m;
    __syncthreads();
    m = fmaxf(fmaxf(sA[rg*4+0],sA[rg*4+1]), fmaxf(sA[rg*4+2],sA[rg*4+3]));

    float e = __expf(v - m);
    float s = e;
    #pragma unroll
    for (int o=16;o>0;o>>=1) s += __shfl_xor_sync(FULL,s,o);
    if (lane==0) sB[w] = s;
    __syncthreads();
    s = sB[rg*4+0]+sB[rg*4+1]+sB[rg*4+2]+sB[rg*4+3];
    float logZ = __logf(s) + m;

    float tg = targ[i];
    float num = tg * (logZ - v);
    float den = tg;
    #pragma unroll
    for (int o=16;o>0;o>>=1){
        num += __shfl_xor_sync(FULL,num,o);
        den += __shfl_xor_sync(FULL,den,o);
    }
    __syncthreads();
    if (lane==0){ sA[w] = num; sB[w] = den; }
    __syncthreads();
    if ((tid & 127) == 0){
        int r = blockIdx.x*2 + rg;
        g_rnum[r] = sA[rg*4+0]+sA[rg*4+1]+sA[rg*4+2]+sA[rg*4+3];
        g_rden[r] = sB[rg*4+0]+sB[rg*4+1]+sB[rg*4+2]+sB[rg*4+3];
    }
}

__global__ __launch_bounds__(256) void k_finalize(float* out){
    int t = threadIdx.x;
    float n=0.f, d=0.f;
    for (int i=t; i<NROWS; i+=256){ n += g_rnum[i]; d += g_rden[i]; }
    __shared__ float sn[256], sd[256];
    sn[t]=n; sd[t]=d; __syncthreads();
    for (int o=128;o>0;o>>=1){
        if (t<o){ sn[t]+=sn[t+o]; sd[t]+=sd[t+o]; }
        __syncthreads();
    }
    if (t==0) out[0] = sn[0]/sd[0];
}

// ---------------------------------------------------------------------------
extern "C" void kernel_launch(void* const* d_in, const int* in_sizes, int n_in,
                              void* d_out, int out_size){
    const float*         seq  = (const float*)d_in[0];
    const int*           att  = (const int*)d_in[1];
    const unsigned char* ng   = (const unsigned char*)d_in[2];
    const float*         targ = (const float*)d_in[3];
    const float*         Wp   = (const float*)d_in[4];
    const float*         bp   = (const float*)d_in[5];
    const float*         Wa   = (const float*)d_in[6];
    const float*         ba   = (const float*)d_in[7];
    const float*         Wout = (const float*)d_in[8];
    float* out = (float*)d_out;

    k_detect<<<1, 256>>>(ng);
    k_prep<<<(PREPTOT+255)/256, 256>>>(seq, Wp, Wa, att, (const void*)ng);
    k_gemm<<<dim3(NTOT/64, Mm/128), 256>>>(bp, ba);
    k_biaffine<<<1024, 128>>>(Wout);

    int wantLoss = (out_size != OUTN) ? 1 : 0;
    int wantOut  = (out_size >= OUTN) ? 1 : 0;
    float* dst = out + ((out_size > OUTN) ? 1 : 0);
    k_combine<<<OUTN/256, 256>>>(targ, dst, wantOut);
    if (wantLoss)
        k_finalize<<<1, 256>>>(out);
}

// round 8
// speedup vs baseline: 1.9135x; 1.0887x over previous
#include <cuda_runtime.h>
#include <cuda_bf16.h>
#include <cuda_fp16.h>
#include <math.h>

#define Bb 2
#define Ss 128
#define Hh 768
#define Cc 5
#define NEGV (-1024.0f)
#define Mm (Bb*Ss)          // 256
#define NTOT (Hh + Cc*Hh)   // 4608
#define NROWS (Bb*Ss*Cc)    // 1280
#define OUTN (Bb*Ss*Cc*Ss)  // 163840

#define KG  (Hh/16)         // 48
#define MI  (Mm/16)         // 16
#define NI8 (NTOT/8)        // 576

#define SEG 8
#define HSEG (Hh/SEG)       // 96
#define JP2 (HSEG/2)        // 48 half2 columns
#define TPB 32              // p rows per tile
#define TAB 8               // a cols per tile

__device__ float g_hp[Mm*Hh];
__device__ float g_ha[Mm*Cc*Hh];
__device__ float g_part[SEG*OUTN];
__device__ float g_rnum[NROWS];
__device__ float g_rden[NROWS];
__device__ float g_maskadd[Bb*Ss*Ss];
__device__ int   g_ngMode;
__device__ unsigned g_ctr;
__device__ unsigned g_Afh[KG*MI*32*4];
__device__ unsigned g_Afl[KG*MI*32*4];
__device__ unsigned g_Bfh[KG*NI8*32*2];
__device__ unsigned g_Bfl[KG*NI8*32*2];

__device__ __forceinline__ unsigned pack2(__nv_bfloat16 lo, __nv_bfloat16 hi){
    __nv_bfloat162 v; v.x = lo; v.y = hi;
    return *reinterpret_cast<unsigned*>(&v);
}
__device__ __forceinline__ void split_bf(float x, __nv_bfloat16& h, __nv_bfloat16& l){
    h = __float2bfloat16(x);
    l = __float2bfloat16(x - __bfloat162float(h));
}

// ---------------------------------------------------------------------------
__global__ __launch_bounds__(256) void k_detect(const unsigned char* __restrict__ ng){
    __shared__ int s_b1, s_f3;
    if (threadIdx.x == 0){ s_b1 = 0; s_f3 = 0; }
    __syncthreads();
    int b1 = 0, f3 = 0;
    for (int i = threadIdx.x; i < 16384; i += 256){
        unsigned char v = ng[i];
        int o = i & 3;
        if (o == 1 && v) b1 = 1;
        if (o == 3 && v == 0x3F) f3 = 1;
    }
    if (b1) s_b1 = 1;
    if (f3) s_f3 = 1;
    __syncthreads();
    if (threadIdx.x == 0) g_ngMode = s_b1 ? 0 : (s_f3 ? 2 : 1);
}

__device__ __forceinline__ bool ng_bit(const void* ng, int idx, int mode){
    if (mode == 1) return ((const int*)ng)[idx] != 0;
    if (mode == 2) return ((const float*)ng)[idx] != 0.0f;
    return ((const unsigned char*)ng)[idx] != 0;
}

// ---------------------------------------------------------------------------
#define AW (KG*MI*32*4)
#define BW (KG*NI8*32*2)
#define MW (Bb*Ss*Ss)
#define PREPTOT (AW+BW+MW)

__global__ __launch_bounds__(256) void k_prep(const float* __restrict__ X,
        const float* __restrict__ Wp, const float* __restrict__ Wa,
        const int* __restrict__ att, const void* __restrict__ ng){
    int idx = blockIdx.x*256 + threadIdx.x;
    if (idx < AW){
        int w = idx;
        int reg = w & 3, lane = (w>>2)&31;
        int tile = w>>7;
        int mi = tile % MI, g = tile / MI;
        int m = mi*16 + (lane>>2) + (reg&1)*8;
        int k = g*16 + (lane&3)*2 + (reg>>1)*8;
        float2 v = *(const float2*)&X[m*Hh + k];
        __nv_bfloat16 hx,lx,hy,ly;
        split_bf(v.x, hx, lx); split_bf(v.y, hy, ly);
        g_Afh[w] = pack2(hx, hy);
        g_Afl[w] = pack2(lx, ly);
    } else if (idx < AW + BW){
        int w = idx - AW;
        int reg = w & 1, lane = (w>>1)&31;
        int tile = w>>6;
        int ni = tile % NI8, g = tile / NI8;
        int n = ni*8 + (lane>>2);
        int k = g*16 + (lane&3)*2 + reg*8;
        float2 v = (n < Hh) ? *(const float2*)&Wp[n*Hh + k]
                            : *(const float2*)&Wa[(n-Hh)*Hh + k];
        __nv_bfloat16 hx,lx,hy,ly;
        split_bf(v.x, hx, lx); split_bf(v.y, hy, ly);
        g_Bfh[w] = pack2(hx, hy);
        g_Bfl[w] = pack2(lx, ly);
    } else if (idx < PREPTOT){
        int w = idx - AW - BW;
        int a = w & 127;
        int bp_ = w >> 7;
        int b = bp_ >> 7;
        int mode = g_ngMode;
        bool attv = att[b*Ss + a] > 0;
        bool m = false;
        #pragma unroll
        for (int c = 0; c < Cc; c++)
            m = m || ng_bit(ng, (bp_*Cc + c)*Ss + a, mode);
        g_maskadd[w] = (m && attv) ? 0.0f : NEGV;
    }
}

// ---------------------------------------------------------------------------
// GEMM: mma m16n8k16 bf16, acc += Ah*Bh + Ah*Bl + Al*Bh, double-buffered
// ---------------------------------------------------------------------------
__device__ __forceinline__ void mma_bf16(float& d0, float& d1, float& d2, float& d3,
        unsigned a0, unsigned a1, unsigned a2, unsigned a3,
        unsigned b0, unsigned b1){
    asm volatile("mma.sync.aligned.m16n8k16.row.col.f32.bf16.bf16.f32 "
        "{%0,%1,%2,%3}, {%4,%5,%6,%7}, {%8,%9}, {%0,%1,%2,%3};"
        : "+f"(d0), "+f"(d1), "+f"(d2), "+f"(d3)
        : "r"(a0), "r"(a1), "r"(a2), "r"(a3), "r"(b0), "r"(b1));
}

__global__ __launch_bounds__(256) void k_gemm(const float* __restrict__ bp,
                                              const float* __restrict__ ba){
    int tid = threadIdx.x;
    int wid = tid >> 5, lane = tid & 31;
    int wr = wid >> 2, wc = wid & 3;
    int mi0 = blockIdx.y*8 + wr*4;
    int ni0 = blockIdx.x*8 + wc*2;

    float acc[4][2][4];
    #pragma unroll
    for (int i=0;i<4;i++) for (int j=0;j<2;j++) for (int q=0;q<4;q++) acc[i][j][q]=0.f;

    const uint4* pAh = reinterpret_cast<const uint4*>(g_Afh);
    const uint4* pAl = reinterpret_cast<const uint4*>(g_Afl);
    const uint2* pBh = reinterpret_cast<const uint2*>(g_Bfh);
    const uint2* pBl = reinterpret_cast<const uint2*>(g_Bfl);

    uint4 Ah[4], Al[4]; uint2 Bh[2], Bl[2];
    #pragma unroll
    for (int mf=0; mf<4; mf++){
        int t = (0*MI + mi0+mf)*32 + lane;
        Ah[mf] = pAh[t]; Al[mf] = pAl[t];
    }
    #pragma unroll
    for (int nf=0; nf<2; nf++){
        int t = (0*NI8 + ni0+nf)*32 + lane;
        Bh[nf] = pBh[t]; Bl[nf] = pBl[t];
    }

    for (int g = 0; g < KG; g++){
        uint4 An[4], Aln[4]; uint2 Bn[2], Bln[2];
        if (g+1 < KG){
            #pragma unroll
            for (int mf=0; mf<4; mf++){
                int t = ((g+1)*MI + mi0+mf)*32 + lane;
                An[mf] = pAh[t]; Aln[mf] = pAl[t];
            }
            #pragma unroll
            for (int nf=0; nf<2; nf++){
                int t = ((g+1)*NI8 + ni0+nf)*32 + lane;
                Bn[nf] = pBh[t]; Bln[nf] = pBl[t];
            }
        }
        #pragma unroll
        for (int mf=0; mf<4; mf++)
            #pragma unroll
            for (int nf=0; nf<2; nf++){
                mma_bf16(acc[mf][nf][0], acc[mf][nf][1], acc[mf][nf][2], acc[mf][nf][3],
                         Ah[mf].x, Ah[mf].y, Ah[mf].z, Ah[mf].w, Bh[nf].x, Bh[nf].y);
                mma_bf16(acc[mf][nf][0], acc[mf][nf][1], acc[mf][nf][2], acc[mf][nf][3],
                         Ah[mf].x, Ah[mf].y, Ah[mf].z, Ah[mf].w, Bl[nf].x, Bl[nf].y);
                mma_bf16(acc[mf][nf][0], acc[mf][nf][1], acc[mf][nf][2], acc[mf][nf][3],
                         Al[mf].x, Al[mf].y, Al[mf].z, Al[mf].w, Bh[nf].x, Bh[nf].y);
            }
        if (g+1 < KG){
            #pragma unroll
            for (int mf=0; mf<4; mf++){ Ah[mf]=An[mf]; Al[mf]=Aln[mf]; }
            #pragma unroll
            for (int nf=0; nf<2; nf++){ Bh[nf]=Bn[nf]; Bl[nf]=Bln[nf]; }
        }
    }

    int r = lane >> 2, c2 = (lane & 3)*2;
    #pragma unroll
    for (int nf=0; nf<2; nf++){
        int n = (ni0+nf)*8 + c2;
        float2 bias = (n < Hh) ? *(const float2*)&bp[n] : *(const float2*)&ba[n-Hh];
        #pragma unroll
        for (int mf=0; mf<4; mf++){
            int m1 = (mi0+mf)*16 + r;
            int m2 = m1 + 8;
            float2 v1 = { acc[mf][nf][0] + bias.x, acc[mf][nf][1] + bias.y };
            float2 v2 = { acc[mf][nf][2] + bias.x, acc[mf][nf][3] + bias.y };
            if (n < Hh){
                *(float2*)&g_hp[m1*Hh + n] = v1;
                *(float2*)&g_hp[m2*Hh + n] = v2;
            } else {
                *(float2*)&g_ha[m1*(Cc*Hh) + (n-Hh)] = v1;
                *(float2*)&g_ha[m2*(Cc*Hh) + (n-Hh)] = v2;
            }
        }
    }
}

// ---------------------------------------------------------------------------
// biaffine partial: all-f16x2 datapath. 8-way h-split, tile 32p x 8a,
// 128 threads (each covers p and p+16). Single smem chunk of 96 h.
// grid = 1024: seg = bx&7; rest = bx>>3 -> b, ptile(4), atile(16)
// ---------------------------------------------------------------------------
__global__ __launch_bounds__(128,8) void k_biaffine(const float* __restrict__ Wout){
    __shared__ __half2 s_hp[TPB][JP2+1];       // pad: rows land in distinct banks
    __shared__ __half2 s_ha[Cc][JP2][TAB];     // lanes read 8 consecutive -> cf
    __shared__ __half2 s_w[Cc][JP2];           // broadcast
    int bx = blockIdx.x;
    int seg  = bx & 7;
    int rest = bx >> 3;               // 0..127
    int b   = rest >> 6;
    int rem = rest & 63;
    int p0 = (rem >> 4) * TPB;
    int a0 = (rem & 15) * TAB;
    int tid = threadIdx.x;
    int p = tid >> 3, a = tid & 7;    // p 0..15, a 0..7
    int hbase = seg * HSEG;

    #pragma unroll
    for (int i = 0; i < 12; i++){                 // 32*48 = 1536 half2
        int idx = tid + i*128;
        int r = idx / JP2, jp = idx % JP2;
        float2 v = *(const float2*)&g_hp[(b*Ss + p0 + r)*Hh + hbase + 2*jp];
        s_hp[r][jp] = __floats2half2_rn(v.x, v.y);
    }
    #pragma unroll
    for (int i = 0; i < 15; i++){                 // 8*5*48 = 1920 half2
        int idx = tid + i*128;
        int al = idx / (Cc*JP2);
        int rr = idx % (Cc*JP2);
        int c = rr / JP2, jp = rr % JP2;
        float2 v = *(const float2*)&g_ha[((b*Ss + a0 + al)*Cc + c)*Hh + hbase + 2*jp];
        s_ha[c][jp][al] = __floats2half2_rn(v.x, v.y);
    }
    for (int idx = tid; idx < Cc*JP2; idx += 128){
        int c = idx / JP2, jp = idx % JP2;
        float2 v = *(const float2*)&Wout[c*Hh + hbase + 2*jp];
        s_w[c][jp] = __floats2half2_rn(v.x, v.y);
    }
    __syncthreads();

    float fA[Cc] = {}, fB[Cc] = {};
    #pragma unroll 1
    for (int blk = 0; blk < 4; blk++){            // 4 blocks of 12 jp
        __half2 accA[Cc], accB[Cc];
        #pragma unroll
        for (int c=0;c<Cc;c++){
            accA[c] = __floats2half2_rn(0.f, 0.f);
            accB[c] = __floats2half2_rn(0.f, 0.f);
        }
        #pragma unroll
        for (int j=0;j<12;j++){
            int jp = blk*12 + j;
            __half2 hpA = s_hp[p][jp];
            __half2 hpB = s_hp[p+16][jp];
            #pragma unroll
            for (int c=0;c<Cc;c++){
                __half2 ha = s_ha[c][jp][a];
                __half2 w  = s_w[c][jp];
                __half2 xA = __hadd2(hpA, ha);
                __half2 xB = __hadd2(hpB, ha);
                unsigned tA, tB;
                asm("tanh.approx.f16x2 %0, %1;" : "=r"(tA) : "r"(*(unsigned*)&xA));
                asm("tanh.approx.f16x2 %0, %1;" : "=r"(tB) : "r"(*(unsigned*)&xB));
                accA[c] = __hfma2(*(__half2*)&tA, w, accA[c]);
                accB[c] = __hfma2(*(__half2*)&tB, w, accB[c]);
            }
        }
        #pragma unroll
        for (int c=0;c<Cc;c++){
            float2 vA = __half22float2(accA[c]);
            float2 vB = __half22float2(accB[c]);
            fA[c] += vA.x + vA.y;
            fB[c] += vB.x + vB.y;
        }
    }
    int pgA = p0 + p, pgB = p0 + p + 16, ag = a0 + a;
    #pragma unroll
    for (int c=0;c<Cc;c++){
        g_part[seg*OUTN + ((b*Ss+pgA)*Cc + c)*Ss + ag] = fA[c];
        g_part[seg*OUTN + ((b*Ss+pgB)*Cc + c)*Ss + ag] = fB[c];
    }
}

// ---------------------------------------------------------------------------
// combine: sum 8 partials + maskadd, write dst, fused row log-softmax CE,
// and last-block finalize (fence+counter).
// ---------------------------------------------------------------------------
#define NBLK (OUTN/256)   // 640

__global__ __launch_bounds__(256) void k_combine(const float* __restrict__ targ,
        float* __restrict__ dst, float* __restrict__ out,
        int writeOut, int writeLoss){
    const unsigned FULL = 0xffffffffu;
    int tid = threadIdx.x;
    int i = blockIdx.x*256 + tid;
    float v = 0.f;
    #pragma unroll
    for (int k=0;k<SEG;k++) v += g_part[k*OUTN + i];
    int a = i & 127;
    int row = i >> 7;
    int bp = row / Cc;
    v += g_maskadd[bp*Ss + a];
    if (writeOut) dst[i] = v;

    int w = tid >> 5, lane = tid & 31, rg = tid >> 7;
    __shared__ float sA[8], sB[8];

    float m = v;
    #pragma unroll
    for (int o=16;o>0;o>>=1) m = fmaxf(m, __shfl_xor_sync(FULL,m,o));
    if (lane==0) sA[w] = m;
    __syncthreads();
    m = fmaxf(fmaxf(sA[rg*4+0],sA[rg*4+1]), fmaxf(sA[rg*4+2],sA[rg*4+3]));

    float e = __expf(v - m);
    float s = e;
    #pragma unroll
    for (int o=16;o>0;o>>=1) s += __shfl_xor_sync(FULL,s,o);
    if (lane==0) sB[w] = s;
    __syncthreads();
    s = sB[rg*4+0]+sB[rg*4+1]+sB[rg*4+2]+sB[rg*4+3];
    float logZ = __logf(s) + m;

    float tg = targ[i];
    float num = tg * (logZ - v);
    float den = tg;
    #pragma unroll
    for (int o=16;o>0;o>>=1){
        num += __shfl_xor_sync(FULL,num,o);
        den += __shfl_xor_sync(FULL,den,o);
    }
    __syncthreads();
    if (lane==0){ sA[w] = num; sB[w] = den; }
    __syncthreads();
    if ((tid & 127) == 0){
        int r = blockIdx.x*2 + rg;
        g_rnum[r] = sA[rg*4+0]+sA[rg*4+1]+sA[rg*4+2]+sA[rg*4+3];
        g_rden[r] = sB[rg*4+0]+sB[rg*4+1]+sB[rg*4+2]+sB[rg*4+3];
    }

    // last-block finalize
    __threadfence();
    __shared__ unsigned s_rank;
    if (tid == 0) s_rank = atomicAdd(&g_ctr, 1u);
    __syncthreads();
    if (s_rank == NBLK-1){
        float n=0.f, d=0.f;
        for (int r = tid; r < NROWS; r += 256){ n += g_rnum[r]; d += g_rden[r]; }
        __shared__ float sn[256], sd[256];
        sn[tid]=n; sd[tid]=d; __syncthreads();
        for (int o=128;o>0;o>>=1){
            if (tid<o){ sn[tid]+=sn[tid+o]; sd[tid]+=sd[tid+o]; }
            __syncthreads();
        }
        if (tid==0){
            if (writeLoss) out[0] = sn[0]/sd[0];
            g_ctr = 0;                       // reset for graph replay
        }
    }
}

// ---------------------------------------------------------------------------
extern "C" void kernel_launch(void* const* d_in, const int* in_sizes, int n_in,
                              void* d_out, int out_size){
    const float*         seq  = (const float*)d_in[0];
    const int*           att  = (const int*)d_in[1];
    const unsigned char* ng   = (const unsigned char*)d_in[2];
    const float*         targ = (const float*)d_in[3];
    const float*         Wp   = (const float*)d_in[4];
    const float*         bp   = (const float*)d_in[5];
    const float*         Wa   = (const float*)d_in[6];
    const float*         ba   = (const float*)d_in[7];
    const float*         Wout = (const float*)d_in[8];
    float* out = (float*)d_out;

    k_detect<<<1, 256>>>(ng);
    k_prep<<<(PREPTOT+255)/256, 256>>>(seq, Wp, Wa, att, (const void*)ng);
    k_gemm<<<dim3(NTOT/64, Mm/128), 256>>>(bp, ba);
    k_biaffine<<<1024, 128>>>(Wout);

    int wantLoss = (out_size != OUTN) ? 1 : 0;
    int wantOut  = (out_size >= OUTN) ? 1 : 0;
    float* dst = out + ((out_size > OUTN) ? 1 : 0);
    k_combine<<<NBLK, 256>>>(targ, dst, out, wantOut, wantLoss);
}